// round 17
// baseline (speedup 1.0000x reference)
#include <cuda_runtime.h>
#include <cuda_bf16.h>
#include <cstdint>

// Problem constants (fixed by the dataset)
#define B_  16
#define D_  128
#define T_  4096
#define BT_ (B_*T_)          // 65536 rows
#define K_  1024
#define NT1 (BT_/128)        // 512 pass1 tiles
#define NT2 (BT_/64)         // 1024 pass2 tiles
#define NCAND 6
#define DELTA 1.5e-4f
#define APITCHB 272          // bf16 MMA tile row pitch
#define P2P 68               // pass2 qs pitch in floats
#define RGRID 1024           // resolver blocks

// ---------------------------------------------------------------------------
// Device scratch
// ---------------------------------------------------------------------------
__device__ float  g_wnorm[K_];                           // fl32(||w||^2)
__device__ __align__(16) __nv_bfloat16 g_Wb[K_ * D_];    // bf16 codebook [k][d]
__device__ int    g_idx[BT_];                            // final argmin per row
__device__ int    g_flagq[BT_];
__device__ int    g_flagn = 0;
__device__ double g_lsum = 0.0;
__device__ unsigned g_done = 0;

__device__ __forceinline__ uint32_t smem_u32(const void* p) {
    uint32_t a;
    asm("{ .reg .u64 t; cvta.to.shared.u64 t, %1; cvt.u32.u64 %0, t; }" : "=r"(a) : "l"(p));
    return a;
}
__device__ __forceinline__ void cp_async16(uint32_t dst, const void* src) {
    asm volatile("cp.async.cg.shared.global [%0], [%1], 16;" :: "r"(dst), "l"(src));
}
#define CP_COMMIT() asm volatile("cp.async.commit_group;" ::: "memory")
#define CP_WAIT(N)  asm volatile("cp.async.wait_group %0;" :: "n"(N) : "memory")

// ascending top-3 (strict < keeps earlier/lower-k entry on ties)
__device__ __forceinline__ void insert3(float v, int k, float* cv, int* ck) {
    if (v < cv[2]) {
        cv[2] = v; ck[2] = k;
        #pragma unroll
        for (int a = 2; a > 0; a--) {
            bool sw = cv[a] < cv[a - 1];
            float tv = sw ? cv[a] : cv[a - 1];
            float tu = sw ? cv[a - 1] : cv[a];
            int   tk = sw ? ck[a] : ck[a - 1];
            int   tl = sw ? ck[a - 1] : ck[a];
            cv[a - 1] = tv; cv[a] = tu;
            ck[a - 1] = tk; ck[a] = tl;
        }
    }
}
// ascending top-6 (merge phase only)
__device__ __forceinline__ void insert6(float v, int k, float* cv, int* ck) {
    if (v < cv[5]) {
        cv[5] = v; ck[5] = k;
        #pragma unroll
        for (int a = 5; a > 0; a--) {
            bool sw = cv[a] < cv[a - 1];
            float tv = sw ? cv[a] : cv[a - 1];
            float tu = sw ? cv[a - 1] : cv[a];
            int   tk = sw ? ck[a] : ck[a - 1];
            int   tl = sw ? ck[a - 1] : ck[a];
            cv[a - 1] = tv; cv[a] = tu;
            ck[a - 1] = tk; ck[a] = tl;
        }
    }
}

// ---------------------------------------------------------------------------
// Kernel 1: ||w||^2 (fp64->fp32, correctly rounded) + bf16 codebook.
// Resets the flag queue counter for this replay.
// ---------------------------------------------------------------------------
__global__ void prep_w_kernel(const float* __restrict__ W) {
    if (blockIdx.x == 0 && threadIdx.x == 0 && threadIdx.y == 0) g_flagn = 0;
    int k = blockIdx.x * 8 + threadIdx.y;
    int lane = threadIdx.x;
    float4 v = *(const float4*)(W + (size_t)k * D_ + lane * 4);
    __nv_bfloat16 b4[4] = { __float2bfloat16(v.x), __float2bfloat16(v.y),
                            __float2bfloat16(v.z), __float2bfloat16(v.w) };
    *(uint2*)(g_Wb + (size_t)k * D_ + lane * 4) = *(uint2*)b4;
    double s = (double)v.x * v.x + (double)v.y * v.y
             + (double)v.z * v.z + (double)v.w * v.w;
    #pragma unroll
    for (int o = 16; o > 0; o >>= 1) s += __shfl_down_sync(0xffffffffu, s, o);
    if (lane == 0) g_wnorm[k] = (float)s;
}

// ---------------------------------------------------------------------------
// Kernel 2: HMMA pass-1 + in-kernel exact resolve for non-flagged rows.
// Mainloop identical to the measured ~102us version. Tail: re-stage fp32 x
// into the dead B buffers, xnorm (4x32 double partials, fixed combine),
// exact sequential-fp32 candidate dots, write g_idx. Flagged rows -> queue.
// ---------------------------------------------------------------------------
#define SM_A    0
#define SM_B0   34816
#define SM_B1   (34816 + 34816)
#define SM_WNS  (34816 + 69632)
#define SM1_TOT (SM_WNS + 4096)     // 108,544

#define MMA_BF16(ACC, A0, A1, A2, A3, B0, B1) \
    asm volatile("mma.sync.aligned.m16n8k16.row.col.f32.bf16.bf16.f32 " \
        "{%0,%1,%2,%3}, {%4,%5,%6,%7}, {%8,%9}, {%0,%1,%2,%3};" \
        : "+f"((ACC)[0]), "+f"((ACC)[1]), "+f"((ACC)[2]), "+f"((ACC)[3]) \
        : "r"(A0), "r"(A1), "r"(A2), "r"(A3), "r"(B0), "r"(B1))

__global__ void __launch_bounds__(256, 2) hmma_pass1_kernel(
        const float* __restrict__ x, const float* __restrict__ W) {
    extern __shared__ char smem[];
    char* sA = smem + SM_A;
    float* xs  = (float*)(smem + SM_B0);        // fp32 x staging (overlays B)
    float* wns = (float*)(smem + SM_WNS);       // [1024]
    int tid = threadIdx.x;
    int warp = tid >> 5, lane = tid & 31;
    int blk = blockIdx.x;
    int b = blk >> 5, t0 = (blk & 31) * 128, r0 = blk * 128;

    const float* xb = x + (size_t)b * D_ * T_ + t0;
    #pragma unroll
    for (int i = 0; i < 16; i++) {
        int lin = i * 256 + tid;
        int d = lin >> 5, t4 = lin & 31;
        *(float4*)(xs + d * 128 + t4 * 4) = *(const float4*)(xb + (size_t)d * T_ + t4 * 4);
    }
    __syncthreads();
    {
        int m = tid >> 1, half = tid & 1;
        #pragma unroll
        for (int cc = 0; cc < 8; cc++) {
            int c = half * 8 + cc;
            __nv_bfloat16 tmp[8];
            #pragma unroll
            for (int j = 0; j < 8; j++) tmp[j] = __float2bfloat16(xs[(c * 8 + j) * 128 + m]);
            *(uint4*)(sA + m * APITCHB + c * 16) = *(uint4*)tmp;
        }
    }
    __syncthreads();
    #pragma unroll
    for (int i = 0; i < 4; i++) wns[i * 256 + tid] = g_wnorm[i * 256 + tid];

    uint32_t sAu = smem_u32(sA);
    uint32_t sB0u = smem_u32(smem + SM_B0), sB1u = smem_u32(smem + SM_B1);
    uint32_t aBase = sAu + (warp * 16 + (lane & 15)) * APITCHB + (lane >> 4) * 16;
    uint32_t bRowOff = ((lane & 7) + (lane >> 4) * 8) * APITCHB + ((lane >> 3) & 1) * 16;

    float cv0[3], cv1[3]; int ck0[3], ck1[3];
    #pragma unroll
    for (int a = 0; a < 3; a++) {
        cv0[a] = 3.4e38f; cv1[a] = 3.4e38f; ck0[a] = 0; ck1[a] = 0;
    }

    #pragma unroll
    for (int i = 0; i < 8; i++) {
        int s = i * 256 + tid;
        int row = s >> 4, c = s & 15;
        cp_async16(sB0u + row * APITCHB + c * 16, g_Wb + (size_t)row * D_ + c * 8);
    }
    CP_COMMIT();

    for (int kt = 0; kt < 8; kt++) {
        if (kt < 7) {
            uint32_t dst = ((kt + 1) & 1) ? sB1u : sB0u;
            const __nv_bfloat16* src = g_Wb + (size_t)(kt + 1) * 128 * D_;
            #pragma unroll
            for (int i = 0; i < 8; i++) {
                int s = i * 256 + tid;
                int row = s >> 4, c = s & 15;
                cp_async16(dst + row * APITCHB + c * 16, src + (size_t)row * D_ + c * 8);
            }
            CP_COMMIT();
            CP_WAIT(1);
        } else {
            CP_WAIT(0);
        }
        __syncthreads();
        uint32_t sBu = (kt & 1) ? sB1u : sB0u;

        float acc[8][2][4];
        #pragma unroll
        for (int np = 0; np < 8; np++)
            #pragma unroll
            for (int h = 0; h < 2; h++)
                #pragma unroll
                for (int q = 0; q < 4; q++) acc[np][h][q] = 0.f;

        #pragma unroll
        for (int ks = 0; ks < 8; ks++) {
            uint32_t af0, af1, af2, af3;
            asm volatile("ldmatrix.sync.aligned.m8n8.x4.shared.b16 {%0,%1,%2,%3}, [%4];"
                : "=r"(af0), "=r"(af1), "=r"(af2), "=r"(af3) : "r"(aBase + ks * 32));
            uint32_t ba[4], bb[4];
            asm volatile("ldmatrix.sync.aligned.m8n8.x4.shared.b16 {%0,%1,%2,%3}, [%4];"
                : "=r"(ba[0]), "=r"(ba[1]), "=r"(ba[2]), "=r"(ba[3])
                : "r"(sBu + ks * 32 + bRowOff));
            #pragma unroll
            for (int np = 0; np < 8; np += 2) {
                asm volatile("ldmatrix.sync.aligned.m8n8.x4.shared.b16 {%0,%1,%2,%3}, [%4];"
                    : "=r"(bb[0]), "=r"(bb[1]), "=r"(bb[2]), "=r"(bb[3])
                    : "r"(sBu + (np + 1) * 16 * APITCHB + ks * 32 + bRowOff));
                MMA_BF16(acc[np][0], af0, af1, af2, af3, ba[0], ba[1]);
                MMA_BF16(acc[np][1], af0, af1, af2, af3, ba[2], ba[3]);
                if (np < 6) {
                    asm volatile("ldmatrix.sync.aligned.m8n8.x4.shared.b16 {%0,%1,%2,%3}, [%4];"
                        : "=r"(ba[0]), "=r"(ba[1]), "=r"(ba[2]), "=r"(ba[3])
                        : "r"(sBu + (np + 2) * 16 * APITCHB + ks * 32 + bRowOff));
                }
                MMA_BF16(acc[np + 1][0], af0, af1, af2, af3, bb[0], bb[1]);
                MMA_BF16(acc[np + 1][1], af0, af1, af2, af3, bb[2], bb[3]);
            }
        }

        #pragma unroll
        for (int np = 0; np < 8; np++) {
            #pragma unroll
            for (int h = 0; h < 2; h++) {
                int k0 = kt * 128 + np * 16 + h * 8 + 2 * (lane & 3);
                float2 wnp = *(const float2*)(wns + k0);
                insert3(fmaf(-2.0f, acc[np][h][0], wnp.x), k0,     cv0, ck0);
                insert3(fmaf(-2.0f, acc[np][h][1], wnp.y), k0 + 1, cv0, ck0);
                insert3(fmaf(-2.0f, acc[np][h][2], wnp.x), k0,     cv1, ck1);
                insert3(fmaf(-2.0f, acc[np][h][3], wnp.y), k0 + 1, cv1, ck1);
            }
        }
        __syncthreads();
    }

    // merge: 4 threads x 3 entries -> top-6 per row (mv/mk in sA region)
    float* mv = (float*)smem;                    // [128][12]
    int*   mk = (int*)(smem + 128 * 12 * 4);     // [128][12]
    __syncthreads();
    {
        int row0 = warp * 16 + (lane >> 2);
        int q = lane & 3;
        #pragma unroll
        for (int a = 0; a < 3; a++) {
            mv[row0 * 12 + q * 3 + a] = cv0[a];  mk[row0 * 12 + q * 3 + a] = ck0[a];
            mv[(row0 + 8) * 12 + q * 3 + a] = cv1[a];  mk[(row0 + 8) * 12 + q * 3 + a] = ck1[a];
        }
    }
    __syncthreads();

    float bv[NCAND]; int bk[NCAND];
    bool risk = false;
    if (tid < 128) {
        #pragma unroll
        for (int a = 0; a < NCAND; a++) { bv[a] = 3.4e38f; bk[a] = 0; }
        #pragma unroll
        for (int i = 0; i < 12; i++)
            insert6(mv[tid * 12 + i], mk[tid * 12 + i], bv, bk);
        float lim = bv[0] + DELTA;
        risk = (bv[5] <= lim);
        #pragma unroll
        for (int q2 = 0; q2 < 4; q2++)
            risk = risk || (mv[tid * 12 + q2 * 3 + 2] <= lim);
    }
    __syncthreads();   // mv/mk reads done (sA region free, not reused anyway)

    // re-stage fp32 x tile into the dead B region (all 256 threads)
    #pragma unroll
    for (int i = 0; i < 16; i++) {
        int lin = i * 256 + tid;
        int d = lin >> 5, t4 = lin & 31;
        *(float4*)(xs + d * 128 + t4 * 4) = *(const float4*)(xb + (size_t)d * T_ + t4 * 4);
    }
    __syncthreads();

    if (tid < 128) {
        int t = tid, r = r0 + tid;
        if (risk) {
            int pos = atomicAdd(&g_flagn, 1);
            g_flagq[pos] = r;
        } else {
            // xnorm: 4 x 32-d double partials, fixed combine (= resolver)
            double sp[4];
            #pragma unroll
            for (int qq = 0; qq < 4; qq++) {
                double s = 0.0;
                #pragma unroll 8
                for (int d = qq * 32; d < qq * 32 + 32; d++) {
                    float v = xs[d * 128 + t]; s += (double)v * (double)v;
                }
                sp[qq] = s;
            }
            float xn = (float)(((sp[0] + sp[1]) + sp[2]) + sp[3]);
            float lim = bv[0] + DELTA;
            float bestv = 3.4e38f; int bestk = 0x7fffffff;
            #pragma unroll
            for (int a = 0; a < NCAND; a++) {
                if (bv[a] <= lim) {
                    int k = bk[a];
                    const float4* w4 = (const float4*)(W + (size_t)k * D_);
                    float acc = 0.f;
                    #pragma unroll
                    for (int d4 = 0; d4 < 32; d4++) {
                        float4 wv = w4[d4];
                        acc = fmaf(xs[(d4 * 4 + 0) * 128 + t], wv.x, acc);
                        acc = fmaf(xs[(d4 * 4 + 1) * 128 + t], wv.y, acc);
                        acc = fmaf(xs[(d4 * 4 + 2) * 128 + t], wv.z, acc);
                        acc = fmaf(xs[(d4 * 4 + 3) * 128 + t], wv.w, acc);
                    }
                    float v = __fsub_rn(__fadd_rn(xn, wns[k]), 2.0f * acc);
                    if (v < bestv || (v == bestv && k < bestk)) { bestv = v; bestk = k; }
                }
            }
            g_idx[r] = bestk;
        }
    }
}

// ---------------------------------------------------------------------------
// Kernel 3: resolver — one block per flagged row (grid-strided). Exact fp32
// full scan (256 thr x 4 codes, lex (v,k) min = first-index semantics).
// ---------------------------------------------------------------------------
__global__ void __launch_bounds__(256) resolver_kernel(
        const float* __restrict__ x, const float* __restrict__ W) {
    __shared__ float xrow[128];
    __shared__ double xnp[4];
    __shared__ float wv8[8];
    __shared__ int   wk8[8];
    int tid = threadIdx.x;
    int n = g_flagn;
    for (int i = blockIdx.x; i < n; i += gridDim.x) {
        int r = g_flagq[i];
        int b = r >> 12, t = r & (T_ - 1);
        if (tid < 128)
            xrow[tid] = x[(size_t)b * D_ * T_ + (size_t)tid * T_ + t];
        __syncthreads();
        if (tid < 4) {
            double s = 0.0;
            #pragma unroll 8
            for (int d = tid * 32; d < tid * 32 + 32; d++) {
                float v = xrow[d]; s += (double)v * (double)v;
            }
            xnp[tid] = s;
        }
        __syncthreads();
        float xn = (float)(((xnp[0] + xnp[1]) + xnp[2]) + xnp[3]);
        float bv = 3.4e38f; int bk = 0x7fffffff;
        #pragma unroll
        for (int j = 0; j < 4; j++) {
            int k = tid * 4 + j;                 // ascending k per thread
            const float4* w4 = (const float4*)(W + (size_t)k * D_);
            float acc = 0.f;
            #pragma unroll
            for (int d4 = 0; d4 < 32; d4++) {
                float4 wv = w4[d4];
                acc = fmaf(xrow[d4 * 4 + 0], wv.x, acc);
                acc = fmaf(xrow[d4 * 4 + 1], wv.y, acc);
                acc = fmaf(xrow[d4 * 4 + 2], wv.z, acc);
                acc = fmaf(xrow[d4 * 4 + 3], wv.w, acc);
            }
            float v = __fsub_rn(__fadd_rn(xn, g_wnorm[k]), 2.0f * acc);
            if (v < bv || (v == bv && k < bk)) { bv = v; bk = k; }
        }
        #pragma unroll
        for (int o = 16; o > 0; o >>= 1) {
            float v = __shfl_down_sync(0xffffffffu, bv, o);
            int   k = __shfl_down_sync(0xffffffffu, bk, o);
            if (v < bv || (v == bv && k < bk)) { bv = v; bk = k; }
        }
        if ((tid & 31) == 0) { wv8[tid >> 5] = bv; wk8[tid >> 5] = bk; }
        __syncthreads();
        if (tid == 0) {
            float fbv = wv8[0]; int fbk = wk8[0];
            #pragma unroll
            for (int w2 = 1; w2 < 8; w2++) {
                float v = wv8[w2]; int k = wk8[w2];
                if (v < fbv || (v == fbv && k < fbk)) { fbv = v; fbk = k; }
            }
            g_idx[r] = fbk;
        }
        __syncthreads();
    }
}

// ---------------------------------------------------------------------------
// Kernel 4: pure streaming output: gather W rows by g_idx, write
// out = fl(x + fl(q - x)), loss partials + ticket. 64-t tiles, 256 thr.
// ---------------------------------------------------------------------------
__global__ void __launch_bounds__(256) pass2_out_kernel(const float* __restrict__ x,
        const float* __restrict__ W, float* __restrict__ out, float* __restrict__ out_idx_f) {
    __shared__ float qs[128 * P2P];      // 34816 B
    __shared__ int idxs[64];
    __shared__ double red[256];
    int tid = threadIdx.x;
    int blk = blockIdx.x;
    int b = blk >> 6, t0 = (blk & 63) * 64, r0 = blk * 64;

    if (tid < 64) {
        int k = g_idx[r0 + tid];
        idxs[tid] = k;
        out_idx_f[r0 + tid] = (float)k;
    }
    __syncthreads();

    // gather W rows -> qs[d][t]
    #pragma unroll
    for (int i = 0; i < 8; i++) {
        int s = i * 256 + tid;
        int row = s & 63, c4 = s >> 6;
        float4 qv = *(const float4*)(W + (size_t)idxs[row] * D_ + c4 * 4);
        qs[(c4 * 4 + 0) * P2P + row] = qv.x;
        qs[(c4 * 4 + 1) * P2P + row] = qv.y;
        qs[(c4 * 4 + 2) * P2P + row] = qv.z;
        qs[(c4 * 4 + 3) * P2P + row] = qv.w;
    }
    __syncthreads();

    // stream x once, write out (coalesced along t), loss partials
    double lsum = 0.0;
    {
        int tt = tid & 63, dg = tid >> 6;
        const float* xbp = x + (size_t)b * D_ * T_ + t0;
        float* ob = out + (size_t)b * D_ * T_ + t0;
        #pragma unroll 8
        for (int p = 0; p < 32; p++) {
            int d = dg * 32 + p;
            float xv = xbp[(size_t)d * T_ + tt];
            float qv = qs[d * P2P + tt];
            float df = __fsub_rn(qv, xv);
            ob[(size_t)d * T_ + tt] = __fadd_rn(xv, df);   // straight-through rounding
            float sq = __fmul_rn(df, df);
            lsum += (double)sq;
        }
    }
    red[tid] = lsum;
    __syncthreads();
    #pragma unroll
    for (int s = 128; s > 0; s >>= 1) {
        if (tid < s) red[tid] += red[tid + s];
        __syncthreads();
    }
    if (tid == 0) {
        atomicAdd(&g_lsum, red[0]);
        __threadfence();
        unsigned tk = atomicAdd(&g_done, 1u);
        if (tk == NT2 - 1) {
            __threadfence();
            double s = *(volatile double*)&g_lsum;
            g_lsum = 0.0;
            g_done = 0;
            out[(size_t)B_ * D_ * T_ + BT_] =
                (float)(s * 0.25 / (double)((size_t)B_ * D_ * T_));
        }
    }
}

// ---------------------------------------------------------------------------
extern "C" void kernel_launch(void* const* d_in, const int* in_sizes, int n_in,
                              void* d_out, int out_size) {
    const float* x = (const float*)d_in[0];   // (B, D, T) fp32
    const float* W = (const float*)d_in[1];   // (K, D)    fp32
    float* out = (float*)d_out;               // [quantized | indices | loss]

    cudaFuncSetAttribute(hmma_pass1_kernel, cudaFuncAttributeMaxDynamicSharedMemorySize, SM1_TOT);

    prep_w_kernel<<<K_ / 8, dim3(32, 8)>>>(W);
    hmma_pass1_kernel<<<NT1, 256, SM1_TOT>>>(x, W);
    resolver_kernel<<<RGRID, 256>>>(x, W);
    pass2_out_kernel<<<NT2, 256>>>(x, W, out, out + (size_t)B_ * D_ * T_);
}